// round 7
// baseline (speedup 1.0000x reference)
#include <cuda_runtime.h>

// CRF NLL: B=1024, T=512, K=64, START=62, STOP=63
// Exp-domain forward recursion. DUAL-STREAM persistent warps: 128 CTAs x 4
// warps = 512 warps; warp gw processes batches order[2gw] (A, longer) and
// order[2gw+1] (B) SIMULTANEOUSLY, interleaved per chunk so stream B's
// instructions fill stream A's stall cycles (and vice versa). Et = exp(trans)
// register-resident once per warp, SHARED by both streams.

#define B_ 1024
#define T_ 512
#define K_ 64
#define START_ 62
#define STOP_ 63

typedef unsigned long long u64;

__device__ int g_order[B_];

__device__ __forceinline__ u64 fma2(u64 a, u64 b, u64 c) {
    u64 d;
    asm("fma.rn.f32x2 %0, %1, %2, %3;" : "=l"(d) : "l"(a), "l"(b), "l"(c));
    return d;
}
__device__ __forceinline__ u64 pack2(float lo, float hi) {
    u64 d;
    asm("mov.b64 %0, {%1, %2};" : "=l"(d) : "f"(lo), "f"(hi));
    return d;
}
__device__ __forceinline__ float sum2(u64 a) {
    float lo, hi;
    asm("mov.b64 {%0, %1}, %2;" : "=f"(lo), "=f"(hi) : "l"(a));
    return lo + hi;
}
__device__ __forceinline__ float pmax2(u64 a) {   // max of 2 packed floats (>=0)
    float lo, hi;
    asm("mov.b64 {%0, %1}, %2;" : "=f"(lo), "=f"(hi) : "l"(a));
    return fmaxf(lo, hi);
}

// Rank batches by descending length; zero the output accumulator.
__global__ void order_kernel(const int* __restrict__ lengths, float* out) {
    __shared__ int L[B_];
    const int tid = threadIdx.x;                 // 256 threads, grid 4
    for (int j = tid; j < B_; j += 256) L[j] = lengths[j];
    __syncthreads();
    const int b = blockIdx.x * 256 + tid;
    const int mylen = L[b];
    int rank = 0;
    for (int j = 0; j < B_; ++j) {
        int lj = L[j];
        rank += (lj > mylen) || (lj == mylen && j < b);
    }
    g_order[rank] = b;
    if (b == 0) out[0] = 0.0f;
}

__global__ void __launch_bounds__(128, 1) crf_dual(
    const float* __restrict__ feats,      // [B,T,K]
    const int*   __restrict__ lengths,    // [B]
    const int*   __restrict__ tags,       // [B,T]
    const float* __restrict__ trans,      // [K,K] trans[next, prev]
    float* __restrict__ out)
{
    __shared__ __align__(16) float vbuf[4][2][2][64];  // [warp][stream][buf][64]

    const int lane = threadIdx.x & 31;    // owns rows 2*lane, 2*lane+1
    const int w    = threadIdx.x >> 5;
    const int gw   = blockIdx.x * 4 + w;  // 0..511, one pair per warp
    float (*vbA)[64] = vbuf[w][0];
    float (*vbB)[64] = vbuf[w][1];

    // ---- Et rows 2*lane, 2*lane+1 (shared by both streams) ----
    u64 EtA2[32], EtB2[32];
#pragma unroll
    for (int q = 0; q < 32; ++q) {
        EtA2[q] = pack2(__expf(trans[(2 * lane)     * K_ + 2 * q]),
                        __expf(trans[(2 * lane)     * K_ + 2 * q + 1]));
        EtB2[q] = pack2(__expf(trans[(2 * lane + 1) * K_ + 2 * q]),
                        __expf(trans[(2 * lane + 1) * K_ + 2 * q + 1]));
    }

    // ---- the pair: A = longer (descending order), B = shorter ----
    const int bA = g_order[2 * gw], bB = g_order[2 * gw + 1];
    const int lenA = lengths[bA],  lenB = lengths[bB];

    const float*  fbA  = feats + (size_t)bA * (T_ * K_);
    const float*  fbB  = feats + (size_t)bB * (T_ * K_);
    const float2* fbA2 = (const float2*)fbA;
    const float2* fbB2 = (const float2*)fbB;
    const int*    tbA  = tags + (size_t)bA * T_;
    const int*    tbB  = tags + (size_t)bB * T_;

    // ---- gold scores, parallel over t ----
    float goldA = 0.0f, goldB = 0.0f;
#pragma unroll
    for (int q = 0; q < 16; ++q) {
        int t = lane + 32 * q;
        if (t < lenA) {
            int tg = tbA[t], pv = t ? tbA[t - 1] : START_;
            goldA += fbA[t * K_ + tg] + trans[tg * K_ + pv];
        }
        if (t < lenB) {
            int tg = tbB[t], pv = t ? tbB[t - 1] : START_;
            goldB += fbB[t * K_ + tg] + trans[tg * K_ + pv];
        }
    }
    if (lane == 0) {
        goldA += trans[STOP_ * K_ + tbA[lenA - 1]];
        goldB += trans[STOP_ * K_ + tbB[lenB - 1]];
    }

    // ---- v0 for both streams ----
    {
        float2 v0;
        v0.x = (2 * lane     == START_) ? 1.0f : 0.0f;
        v0.y = (2 * lane + 1 == START_) ? 1.0f : 0.0f;
        ((float2*)vbA[0])[lane] = v0;
        ((float2*)vbB[0])[lane] = v0;
    }

    // ---- emission rings: exp'd current group; raw next group loaded in-loop
    float2 ceA0, ceA1, ceA2, ceA3, ceB0, ceB1, ceB2, ceB3;
    {
        float2 r0 = fbA2[0 * 32 + lane], r1 = fbA2[1 * 32 + lane],
               r2 = fbA2[2 * 32 + lane], r3 = fbA2[3 * 32 + lane];
        ceA0 = make_float2(__expf(r0.x), __expf(r0.y));
        ceA1 = make_float2(__expf(r1.x), __expf(r1.y));
        ceA2 = make_float2(__expf(r2.x), __expf(r2.y));
        ceA3 = make_float2(__expf(r3.x), __expf(r3.y));
        r0 = fbB2[0 * 32 + lane]; r1 = fbB2[1 * 32 + lane];
        r2 = fbB2[2 * 32 + lane]; r3 = fbB2[3 * 32 + lane];
        ceB0 = make_float2(__expf(r0.x), __expf(r0.y));
        ceB1 = make_float2(__expf(r1.x), __expf(r1.y));
        ceB2 = make_float2(__expf(r2.x), __expf(r2.y));
        ceB3 = make_float2(__expf(r3.x), __expf(r3.y));
    }
    __syncwarp();

    int ktA = 0, ktB = 0, curA = 0, curB = 0;
    const int lenA4 = lenA & ~3;
    const int lenB4 = lenB & ~3;

    // Dual step: both streams advanced, chunk-interleaved. ONE syncwarp.
#define DUAL_STEP(CEA, CEB, RESC)                                          \
    {                                                                      \
        const ulonglong2* vvA = (const ulonglong2*)vbA[curA];              \
        const ulonglong2* vvB = (const ulonglong2*)vbB[curB];              \
        u64 aA0 = 0ull, aA1 = 0ull, aB0 = 0ull, aB1 = 0ull;                \
        float mxA = 0.f, mxB = 0.f;                                        \
        _Pragma("unroll")                                                  \
        for (int h = 0; h < 4; ++h) {                                      \
            ulonglong2 xA[4], xB[4];                                       \
            _Pragma("unroll")                                              \
            for (int q = 0; q < 4; ++q) xA[q] = vvA[4 * h + q];            \
            _Pragma("unroll")                                              \
            for (int q = 0; q < 4; ++q) xB[q] = vvB[4 * h + q];            \
            _Pragma("unroll")                                              \
            for (int q = 0; q < 4; ++q) {                                  \
                const int j = 4 * h + q;                                   \
                aA0 = fma2(EtA2[2 * j],     xA[q].x, aA0);                 \
                aA1 = fma2(EtB2[2 * j],     xA[q].x, aA1);                 \
                aB0 = fma2(EtA2[2 * j],     xB[q].x, aB0);                 \
                aB1 = fma2(EtB2[2 * j],     xB[q].x, aB1);                 \
                aA0 = fma2(EtA2[2 * j + 1], xA[q].y, aA0);                 \
                aA1 = fma2(EtB2[2 * j + 1], xA[q].y, aA1);                 \
                aB0 = fma2(EtA2[2 * j + 1], xB[q].y, aB0);                 \
                aB1 = fma2(EtB2[2 * j + 1], xB[q].y, aB1);                 \
                if (RESC) {                                                \
                    mxA = fmaxf(mxA, fmaxf(pmax2(xA[q].x), pmax2(xA[q].y)));\
                    mxB = fmaxf(mxB, fmaxf(pmax2(xB[q].x), pmax2(xB[q].y)));\
                }                                                          \
            }                                                              \
        }                                                                  \
        float wA0 = sum2(aA0) * (CEA).x, wA1 = sum2(aA1) * (CEA).y;        \
        float wB0 = sum2(aB0) * (CEB).x, wB1 = sum2(aB1) * (CEB).y;        \
        if (RESC) {                                                        \
            if (mxA > 0.0f) {                                              \
                int k = ((__float_as_int(mxA) >> 23) & 0xFF) - 127;        \
                ktA += k;                                                  \
                float sc = __int_as_float((127 - k) << 23);                \
                wA0 *= sc; wA1 *= sc;                                      \
            }                                                              \
            if (mxB > 0.0f) {                                              \
                int k = ((__float_as_int(mxB) >> 23) & 0xFF) - 127;        \
                ktB += k;                                                  \
                float sc = __int_as_float((127 - k) << 23);                \
                wB0 *= sc; wB1 *= sc;                                      \
            }                                                              \
        }                                                                  \
        curA ^= 1; curB ^= 1;                                              \
        ((float2*)vbA[curA])[lane] = make_float2(wA0, wA1);                \
        ((float2*)vbB[curB])[lane] = make_float2(wB0, wB1);                \
        __syncwarp();                                                      \
    }

    // Single-stream step for tails (S = A or B, token-pasted state).
#define SINGLE_STEP(S, CE, RESC)                                           \
    {                                                                      \
        const ulonglong2* vv = (const ulonglong2*)vb##S[cur##S];           \
        u64 ac0 = 0ull, ac1 = 0ull;                                        \
        float mx = 0.f;                                                    \
        _Pragma("unroll")                                                  \
        for (int h = 0; h < 4; ++h) {                                      \
            ulonglong2 x[4];                                               \
            _Pragma("unroll")                                              \
            for (int q = 0; q < 4; ++q) x[q] = vv[4 * h + q];              \
            _Pragma("unroll")                                              \
            for (int q = 0; q < 4; ++q) {                                  \
                const int j = 4 * h + q;                                   \
                ac0 = fma2(EtA2[2 * j],     x[q].x, ac0);                  \
                ac1 = fma2(EtB2[2 * j],     x[q].x, ac1);                  \
                ac0 = fma2(EtA2[2 * j + 1], x[q].y, ac0);                  \
                ac1 = fma2(EtB2[2 * j + 1], x[q].y, ac1);                  \
                if (RESC) mx = fmaxf(mx, fmaxf(pmax2(x[q].x),              \
                                               pmax2(x[q].y)));            \
            }                                                              \
        }                                                                  \
        float w0 = sum2(ac0) * (CE).x;                                     \
        float w1 = sum2(ac1) * (CE).y;                                     \
        if (RESC && mx > 0.0f) {                                           \
            int k = ((__float_as_int(mx) >> 23) & 0xFF) - 127;             \
            kt##S += k;                                                    \
            float sc = __int_as_float((127 - k) << 23);                    \
            w0 *= sc; w1 *= sc;                                            \
        }                                                                  \
        cur##S ^= 1;                                                       \
        ((float2*)vb##S[cur##S])[lane] = make_float2(w0, w1);              \
        __syncwarp();                                                      \
    }

    // ---- dual main loop: steps 0 .. lenB4-1 on both streams ----
    for (int t0 = 0; t0 < lenB4; t0 += 4) {
        const int p = min(t0 + 4, T_ - 4);     // clamp: garbage rows never used
        float2 gA0 = fbA2[(p + 0) * 32 + lane];
        float2 gA1 = fbA2[(p + 1) * 32 + lane];
        float2 gA2 = fbA2[(p + 2) * 32 + lane];
        float2 gA3 = fbA2[(p + 3) * 32 + lane];
        float2 gB0 = fbB2[(p + 0) * 32 + lane];
        float2 gB1 = fbB2[(p + 1) * 32 + lane];
        float2 gB2 = fbB2[(p + 2) * 32 + lane];
        float2 gB3 = fbB2[(p + 3) * 32 + lane];

        DUAL_STEP(ceA0, ceB0, false);
        DUAL_STEP(ceA1, ceB1, false);
        DUAL_STEP(ceA2, ceB2, false);
        DUAL_STEP(ceA3, ceB3, true);

        ceA0 = make_float2(__expf(gA0.x), __expf(gA0.y));
        ceA1 = make_float2(__expf(gA1.x), __expf(gA1.y));
        ceA2 = make_float2(__expf(gA2.x), __expf(gA2.y));
        ceA3 = make_float2(__expf(gA3.x), __expf(gA3.y));
        ceB0 = make_float2(__expf(gB0.x), __expf(gB0.y));
        ceB1 = make_float2(__expf(gB1.x), __expf(gB1.y));
        ceB2 = make_float2(__expf(gB2.x), __expf(gB2.y));
        ceB3 = make_float2(__expf(gB3.x), __expf(gB3.y));
    }

    // ---- stream B remainder (<=3 steps, no rescale needed) ----
    const int remB = lenB - lenB4;
    if (remB > 0) SINGLE_STEP(B, ceB0, false);
    if (remB > 1) SINGLE_STEP(B, ceB1, false);
    if (remB > 2) SINGLE_STEP(B, ceB2, false);

    // ---- stream A tail groups (rescale cadence preserved: multiples of 4) --
    for (int t0 = lenB4; t0 < lenA4; t0 += 4) {
        const int p = min(t0 + 4, T_ - 4);
        float2 gA0 = fbA2[(p + 0) * 32 + lane];
        float2 gA1 = fbA2[(p + 1) * 32 + lane];
        float2 gA2 = fbA2[(p + 2) * 32 + lane];
        float2 gA3 = fbA2[(p + 3) * 32 + lane];

        SINGLE_STEP(A, ceA0, false);
        SINGLE_STEP(A, ceA1, false);
        SINGLE_STEP(A, ceA2, false);
        SINGLE_STEP(A, ceA3, true);

        ceA0 = make_float2(__expf(gA0.x), __expf(gA0.y));
        ceA1 = make_float2(__expf(gA1.x), __expf(gA1.y));
        ceA2 = make_float2(__expf(gA2.x), __expf(gA2.y));
        ceA3 = make_float2(__expf(gA3.x), __expf(gA3.y));
    }
    const int remA = lenA - lenA4;
    if (remA > 0) SINGLE_STEP(A, ceA0, false);
    if (remA > 1) SINGLE_STEP(A, ceA1, false);
    if (remA > 2) SINGLE_STEP(A, ceA2, false);

#undef DUAL_STEP
#undef SINGLE_STEP

    // ---- terminal for both streams ----
    const float EtS0 = __expf(trans[STOP_ * K_ + 2 * lane]);
    const float EtS1 = __expf(trans[STOP_ * K_ + 2 * lane + 1]);
    float2 vfA = ((float2*)vbA[curA])[lane];   // own stores, program-ordered
    float2 vfB = ((float2*)vbB[curB])[lane];
    float uA = vfA.x * EtS0 + vfA.y * EtS1;
    float uB = vfB.x * EtS0 + vfB.y * EtS1;
#pragma unroll
    for (int off = 16; off; off >>= 1) {
        uA    += __shfl_xor_sync(0xFFFFFFFFu, uA,    off);
        uB    += __shfl_xor_sync(0xFFFFFFFFu, uB,    off);
        goldA += __shfl_xor_sync(0xFFFFFFFFu, goldA, off);
        goldB += __shfl_xor_sync(0xFFFFFFFFu, goldB, off);
    }
    if (lane == 0) {
        const double LN2 = 0.69314718055994530942;
        float fwdA = (float)((double)ktA * LN2) + logf(uA);
        float fwdB = (float)((double)ktB * LN2) + logf(uB);
        atomicAdd(out, ((fwdA - goldA) + (fwdB - goldB)) * (1.0f / (float)B_));
    }
}

extern "C" void kernel_launch(void* const* d_in, const int* in_sizes, int n_in,
                              void* d_out, int out_size)
{
    const float* feats   = (const float*)d_in[0];
    const int*   lengths = (const int*)  d_in[1];
    const int*   tags    = (const int*)  d_in[2];
    const float* trans   = (const float*)d_in[3];
    float* out = (float*)d_out;

    order_kernel<<<4, 256>>>(lengths, out);
    crf_dual<<<128, 128>>>(feats, lengths, tags, trans, out);
}

// round 10
// speedup vs baseline: 1.2748x; 1.2748x over previous
#include <cuda_runtime.h>

// CRF NLL: B=1024, T=512, K=64, START=62, STOP=63
// Exp-domain forward recursion. Persistent warps (148 CTAs x 4 = 592, one per
// SMSP), LPT order via atomic counter. NO shared memory in the recursion:
// v lives in registers (2 elems/lane), broadcast via __shfl_sync per step.
//   per column pair j: shfl lane j's (v[2j],v[2j+1]) -> 2x fma.rn.f32x2.
// Et = exp(trans) register-resident once per warp.

#define B_ 1024
#define T_ 512
#define K_ 64
#define START_ 62
#define STOP_ 63

typedef unsigned long long u64;

__device__ int g_order[B_];
__device__ int g_counter;

__device__ __forceinline__ u64 fma2(u64 a, u64 b, u64 c) {
    u64 d;
    asm("fma.rn.f32x2 %0, %1, %2, %3;" : "=l"(d) : "l"(a), "l"(b), "l"(c));
    return d;
}
__device__ __forceinline__ u64 pack2(float lo, float hi) {
    u64 d;
    asm("mov.b64 %0, {%1, %2};" : "=l"(d) : "f"(lo), "f"(hi));
    return d;
}
__device__ __forceinline__ float sum2(u64 a) {
    float lo, hi;
    asm("mov.b64 {%0, %1}, %2;" : "=f"(lo), "=f"(hi) : "l"(a));
    return lo + hi;
}

// Rank batches by descending length; zero accumulator + work counter.
__global__ void order_kernel(const int* __restrict__ lengths, float* out) {
    __shared__ int L[B_];
    const int tid = threadIdx.x;                 // 256 threads, grid 4
    for (int j = tid; j < B_; j += 256) L[j] = lengths[j];
    __syncthreads();
    const int b = blockIdx.x * 256 + tid;
    const int mylen = L[b];
    int rank = 0;
    for (int j = 0; j < B_; ++j) {
        int lj = L[j];
        rank += (lj > mylen) || (lj == mylen && j < b);
    }
    g_order[rank] = b;
    if (b == 0) { out[0] = 0.0f; g_counter = 0; }
}

__global__ void __launch_bounds__(128, 1) crf_shfl(
    const float* __restrict__ feats,      // [B,T,K]
    const int*   __restrict__ lengths,    // [B]
    const int*   __restrict__ tags,       // [B,T]
    const float* __restrict__ trans,      // [K,K] trans[next, prev]
    float* __restrict__ out)
{
    const int lane = threadIdx.x & 31;    // owns rows/elems 2*lane, 2*lane+1

    // ---- Et rows 2*lane, 2*lane+1, packed over column pairs; ONCE per warp --
    u64 EtA2[32], EtB2[32];
#pragma unroll
    for (int q = 0; q < 32; ++q) {
        EtA2[q] = pack2(__expf(trans[(2 * lane)     * K_ + 2 * q]),
                        __expf(trans[(2 * lane)     * K_ + 2 * q + 1]));
        EtB2[q] = pack2(__expf(trans[(2 * lane + 1) * K_ + 2 * q]),
                        __expf(trans[(2 * lane + 1) * K_ + 2 * q + 1]));
    }
    const float EtS0 = __expf(trans[STOP_ * K_ + 2 * lane]);
    const float EtS1 = __expf(trans[STOP_ * K_ + 2 * lane + 1]);

    for (;;) {
        // ---- grab next batch (longest remaining first) ----
        int r = 0;
        if (lane == 0) r = atomicAdd(&g_counter, 1);
        r = __shfl_sync(0xFFFFFFFFu, r, 0);
        if (r >= B_) break;
        const int b   = g_order[r];
        const int len = lengths[b];

        const float*  fb  = feats + (size_t)b * (T_ * K_);
        const float2* fb2 = (const float2*)fb;          // [T][32]
        const int*    tb  = tags + (size_t)b * T_;

        // ---- gold score, parallel over t ----
        float gold = 0.0f;
#pragma unroll
        for (int q = 0; q < 16; ++q) {
            int t = lane + 32 * q;
            if (t < len) {
                int tg = tb[t];
                int pv = t ? tb[t - 1] : START_;
                gold += fb[t * K_ + tg] + trans[tg * K_ + pv];
            }
        }
        if (lane == 0) gold += trans[STOP_ * K_ + tb[len - 1]];

        // ---- v0 in registers: 1 at START, 0 elsewhere ----
        float w0 = (2 * lane     == START_) ? 1.0f : 0.0f;
        float w1 = (2 * lane + 1 == START_) ? 1.0f : 0.0f;

        // ---- emission group 0..3, exp'd ----
        float2 c0 = fb2[0 * 32 + lane], c1 = fb2[1 * 32 + lane],
               c2 = fb2[2 * 32 + lane], c3 = fb2[3 * 32 + lane];
        float2 ce0 = make_float2(__expf(c0.x), __expf(c0.y));
        float2 ce1 = make_float2(__expf(c1.x), __expf(c1.y));
        float2 ce2 = make_float2(__expf(c2.x), __expf(c2.y));
        float2 ce3 = make_float2(__expf(c3.x), __expf(c3.y));

        int ktot = 0;
        const int len4 = len & ~3;

        // One step: broadcast all 64 v via shfl, fma2 matvec, apply exp(emit).
        // No shared memory, no syncwarp (shfl synchronizes).
#define STEP(CE, RESC)                                                     \
    {                                                                      \
        u64 a0 = 0ull, a1 = 0ull;                                          \
        float mx = 0.0f;                                                   \
        _Pragma("unroll")                                                  \
        for (int j = 0; j < 32; ++j) {                                     \
            float bx = __shfl_sync(0xFFFFFFFFu, w0, j);                    \
            float by = __shfl_sync(0xFFFFFFFFu, w1, j);                    \
            u64 bc = pack2(bx, by);                                        \
            a0 = fma2(EtA2[j], bc, a0);                                    \
            a1 = fma2(EtB2[j], bc, a1);                                    \
            if (RESC) mx = fmaxf(mx, fmaxf(bx, by));                       \
        }                                                                  \
        float nw0 = sum2(a0) * (CE).x;                                     \
        float nw1 = sum2(a1) * (CE).y;                                     \
        if (RESC) {                                                        \
            /* mx identical on every lane: built from broadcast values */  \
            if (mx > 0.0f) {                                               \
                int k = ((__float_as_int(mx) >> 23) & 0xFF) - 127;         \
                ktot += k;                                                 \
                float sc = __int_as_float((127 - k) << 23);                \
                nw0 *= sc; nw1 *= sc;                                      \
            }                                                              \
        }                                                                  \
        w0 = nw0; w1 = nw1;                                                \
    }

        for (int t0 = 0; t0 < len4; t0 += 4) {
            // load next group's raw emissions (clamped; garbage never used)
            const int p = min(t0 + 4, T_ - 4);
            float2 g0 = fb2[(p + 0) * 32 + lane];
            float2 g1 = fb2[(p + 1) * 32 + lane];
            float2 g2 = fb2[(p + 2) * 32 + lane];
            float2 g3 = fb2[(p + 3) * 32 + lane];

            STEP(ce0, false);
            STEP(ce1, false);
            STEP(ce2, false);
            STEP(ce3, true);

            ce0 = make_float2(__expf(g0.x), __expf(g0.y));
            ce1 = make_float2(__expf(g1.x), __expf(g1.y));
            ce2 = make_float2(__expf(g2.x), __expf(g2.y));
            ce3 = make_float2(__expf(g3.x), __expf(g3.y));
        }

        // remainder (0-3 steps; <=3 unscaled steps cannot overflow)
        const int rem = len - len4;
        if (rem > 0) STEP(ce0, false);
        if (rem > 1) STEP(ce1, false);
        if (rem > 2) STEP(ce2, false);
#undef STEP

        // ---- terminal: fwd = ktot*ln2 + log(sum_i v[i]*exp(trans[STOP,i])) --
        float u = w0 * EtS0 + w1 * EtS1;
#pragma unroll
        for (int off = 16; off; off >>= 1) {
            u    += __shfl_xor_sync(0xFFFFFFFFu, u,    off);
            gold += __shfl_xor_sync(0xFFFFFFFFu, gold, off);
        }
        if (lane == 0) {
            float fwd = (float)((double)ktot * 0.69314718055994530942)
                      + logf(u);
            atomicAdd(out, (fwd - gold) * (1.0f / (float)B_));
        }
    }
}

extern "C" void kernel_launch(void* const* d_in, const int* in_sizes, int n_in,
                              void* d_out, int out_size)
{
    const float* feats   = (const float*)d_in[0];
    const int*   lengths = (const int*)  d_in[1];
    const int*   tags    = (const int*)  d_in[2];
    const float* trans   = (const float*)d_in[3];
    float* out = (float*)d_out;

    order_kernel<<<4, 256>>>(lengths, out);
    crf_shfl<<<148, 128>>>(feats, lengths, tags, trans, out);
}